// round 4
// baseline (speedup 1.0000x reference)
#include <cuda_runtime.h>
#include <cstdint>
#include <cstddef>

#define BB 16
#define LL 32768
#define HH 64
#define NN 16
#define DMM 32

typedef unsigned long long u64;

// ---------------- scratch (device globals) ----------------
__device__ float g_u[(size_t)BB * HH * LL];   // gelu(x@W_lin) transposed to [B,H,L]
__device__ float g_z[(size_t)BB * HH * LL];   // FiLM-affine SSM output [B,H,L]
__device__ __align__(16) float g_w1re[HH * NN], g_w1im[HH * NN];
__device__ __align__(16) float g_w2re[HH * NN], g_w2im[HH * NN];
__device__ __align__(16) float g_cre[HH * NN], g_cim[HH * NN];     // 2*C'
__device__ float g_wTre[HH * NN], g_wTim[HH * NN];     // w^128
__device__ float g_wT16re[HH * NN], g_wT16im[HH * NN]; // w^2048
__device__ float g_gamma[BB * HH], g_beta[BB * HH];

// ---------------- f32x2 helpers ----------------
__device__ __forceinline__ u64 pk(float lo, float hi) {
    u64 r; asm("mov.b64 %0, {%1,%2};" : "=l"(r) : "f"(lo), "f"(hi)); return r;
}
__device__ __forceinline__ void upk(u64 a, float& lo, float& hi) {
    asm("mov.b64 {%0,%1}, %2;" : "=f"(lo), "=f"(hi) : "l"(a));
}
__device__ __forceinline__ u64 fma2(u64 a, u64 b, u64 c) {
    u64 d; asm("fma.rn.f32x2 %0, %1, %2, %3;" : "=l"(d) : "l"(a), "l"(b), "l"(c)); return d;
}
__device__ __forceinline__ u64 mul2(u64 a, u64 b) {
    u64 d; asm("mul.rn.f32x2 %0, %1, %2;" : "=l"(d) : "l"(a), "l"(b)); return d;
}
__device__ __forceinline__ u64 add2(u64 a, u64 b) {
    u64 d; asm("add.rn.f32x2 %0, %1, %2;" : "=l"(d) : "l"(a), "l"(b)); return d;
}
#define NEGMASK 0x8000000080000000ULL

// jax.nn.gelu (approximate=True)
__device__ __forceinline__ float gelu_f(float x) {
    float x3 = x * x * x;
    float z = 0.7978845608028654f * fmaf(0.044715f, x3, x);
    float az = fabsf(z);
    float e = __expf(2.0f * az);
    float t = 1.0f - __fdividef(2.0f, e + 1.0f);
    t = copysignf(t, z);
    return 0.5f * x * (1.0f + t);
}

// ---------------- K0: SSM constants ----------------
__global__ void k_setup_ssm(const float* __restrict__ log_dt,
                            const float* __restrict__ A_re, const float* __restrict__ A_im,
                            const float* __restrict__ C_re, const float* __restrict__ C_im)
{
    int i = blockIdx.x * blockDim.x + threadIdx.x;
    if (i >= HH * NN) return;
    int h = i / NN;
    float dt = expf(log_dt[h]);
    float ar = A_re[i], ai = A_im[i];
    double mre = (double)dt * (double)ar, mim = (double)dt * (double)ai;

    double e1 = exp(mre);
    float wre = (float)(e1 * cos(mim)), wim = (float)(e1 * sin(mim));
    g_w1re[i] = wre; g_w1im[i] = wim;
    double e2 = exp(2.0 * mre);
    g_w2re[i] = (float)(e2 * cos(2.0 * mim)); g_w2im[i] = (float)(e2 * sin(2.0 * mim));
    double eT = exp(128.0 * mre);
    g_wTre[i] = (float)(eT * cos(128.0 * mim)); g_wTim[i] = (float)(eT * sin(128.0 * mim));
    double eG = exp(2048.0 * mre);
    g_wT16re[i] = (float)(eG * cos(2048.0 * mim)); g_wT16im[i] = (float)(eG * sin(2048.0 * mim));

    // C' = C * (exp(dtA)-1)/A ; store 2*C'
    float inv = 1.0f / (ar * ar + ai * ai);
    float nre = wre - 1.0f, nim = wim;
    float qre = (nre * ar + nim * ai) * inv;
    float qim = (nim * ar - nre * ai) * inv;
    float cr = C_re[i], ci = C_im[i];
    g_cre[i] = 2.0f * (cr * qre - ci * qim);
    g_cim[i] = 2.0f * (cr * qim + ci * qre);
}

// ---------------- K1: conditioning MLP + FiLM ----------------
__global__ void k_setup_mlp(const float* __restrict__ cp,
                            const float* __restrict__ W0, const float* __restrict__ b0,
                            const float* __restrict__ W1, const float* __restrict__ b1,
                            const float* __restrict__ W2, const float* __restrict__ b2,
                            const float* __restrict__ W_film, const float* __restrict__ b_film)
{
    __shared__ float c0[BB * DMM];
    __shared__ float c1[BB * DMM];
    int t = threadIdx.x;

    for (int i = t; i < BB * DMM; i += blockDim.x) {
        int b = i / DMM, d = i % DMM;
        float v = fmaf(cp[b * 2 + 0], W0[d], fmaf(cp[b * 2 + 1], W0[DMM + d], b0[d]));
        c0[i] = gelu_f(v);
    }
    __syncthreads();
    for (int i = t; i < BB * DMM; i += blockDim.x) {
        int b = i / DMM, d = i % DMM;
        float v = b1[d];
        for (int k = 0; k < DMM; k++) v = fmaf(c0[b * DMM + k], W1[k * DMM + d], v);
        c1[i] = gelu_f(v);
    }
    __syncthreads();
    for (int i = t; i < BB * DMM; i += blockDim.x) {
        int b = i / DMM, d = i % DMM;
        float v = b2[d];
        for (int k = 0; k < DMM; k++) v = fmaf(c1[b * DMM + k], W2[k * DMM + d], v);
        c0[i] = gelu_f(v);
    }
    __syncthreads();
    for (int i = t; i < BB * 2 * HH; i += blockDim.x) {
        int b = i / (2 * HH), j = i % (2 * HH);
        float v = b_film[j];
        for (int k = 0; k < DMM; k++) v = fmaf(c0[b * DMM + k], W_film[k * 2 * HH + j], v);
        if (j < HH) g_gamma[b * HH + j] = v;
        else        g_beta[b * HH + j - HH] = v;
    }
}

// ---------------- K2: u = gelu(x @ W_lin + b_lin), write transposed [B,H,L] ----------------
__global__ __launch_bounds__(256) void k_linear(const float* __restrict__ x,
                                                const float* __restrict__ W,
                                                const float* __restrict__ bias)
{
    extern __shared__ float sm2[];
    float* xs = sm2;                 // [256][65]
    float* Ws = sm2 + 256 * 65;      // [64][64]
    int t = threadIdx.x;
    int b = blockIdx.x >> 7;
    int tile = blockIdx.x & 127;
    int l0 = tile * 256;
    const float* xg = x + ((size_t)b * LL + l0) * HH;

    for (int i = t; i < 64 * 64; i += 256) Ws[i] = W[i];
    for (int i = t; i < 256 * 64; i += 256) {
        int l = i >> 6, k = i & 63;
        xs[l * 65 + k] = xg[i];
    }
    __syncthreads();

    int li = t & 63;
    int hb = (t >> 6) * 16;
    u64 acc[4][8];
    #pragma unroll
    for (int p = 0; p < 8; p++) {
        u64 bp = *reinterpret_cast<const u64*>(bias + hb + 2 * p);
        acc[0][p] = bp; acc[1][p] = bp; acc[2][p] = bp; acc[3][p] = bp;
    }
    for (int k = 0; k < 64; k++) {
        float x0 = xs[li * 65 + k];
        float x1 = xs[(li + 64) * 65 + k];
        float x2v = xs[(li + 128) * 65 + k];
        float x3 = xs[(li + 192) * 65 + k];
        u64 xa = pk(x0, x0), xb = pk(x1, x1), xc = pk(x2v, x2v), xd = pk(x3, x3);
        const u64* wrow = reinterpret_cast<const u64*>(Ws + k * 64 + hb);
        #pragma unroll
        for (int p = 0; p < 8; p++) {
            u64 w2 = wrow[p];
            acc[0][p] = fma2(xa, w2, acc[0][p]);
            acc[1][p] = fma2(xb, w2, acc[1][p]);
            acc[2][p] = fma2(xc, w2, acc[2][p]);
            acc[3][p] = fma2(xd, w2, acc[3][p]);
        }
    }
    #pragma unroll
    for (int lg = 0; lg < 4; lg++) {
        int l = l0 + li + lg * 64;
        #pragma unroll
        for (int p = 0; p < 8; p++) {
            float v0, v1; upk(acc[lg][p], v0, v1);
            int h0 = hb + 2 * p;
            g_u[((size_t)b * HH + h0) * LL + l] = gelu_f(v0);
            g_u[((size_t)b * HH + h0 + 1) * LL + l] = gelu_f(v1);
        }
    }
}

// ---------------- K3: chunked parallel scan per (b,h), half-staged, 2 blocks/SM ----------------
// Thread t owns chunk l = t*128 + j, j = 0..127. SMEM holds 64 j-rows at a time:
// su[j_local*257 + t].  2 blocks/SM (101 KB smem, <=128 regs).
#define SUP 257
__global__ __launch_bounds__(256, 2) void k_scan(const float* __restrict__ Dp)
{
    extern __shared__ float sm[];
    float* su = sm;                                             // [64][257]
    float2* sst = reinterpret_cast<float2*>(sm + 64 * SUP);     // [16][257] float2
    float2* gs = reinterpret_cast<float2*>(sm + 64 * SUP + 16 * SUP * 2); // [16][16]
    int t = threadIdx.x;
    int bh = blockIdx.x;
    int h = bh & 63;

    const float4* gu4 = reinterpret_cast<const float4*>(g_u + (size_t)bh * LL);

    // pass-1 constants
    u64 w1re[8], w1im[8], w2re[8], w2im[8], nw2im[8];
    {
        const u64* p1r = reinterpret_cast<const u64*>(g_w1re + h * NN);
        const u64* p1i = reinterpret_cast<const u64*>(g_w1im + h * NN);
        const u64* p2r = reinterpret_cast<const u64*>(g_w2re + h * NN);
        const u64* p2i = reinterpret_cast<const u64*>(g_w2im + h * NN);
        #pragma unroll
        for (int p = 0; p < 8; p++) {
            w1re[p] = p1r[p]; w1im[p] = p1i[p];
            w2re[p] = p2r[p]; w2im[p] = p2i[p];
            nw2im[p] = p2i[p] ^ NEGMASK;
        }
    }

    u64 sre[8], sim[8];
    #pragma unroll
    for (int p = 0; p < 8; p++) { sre[p] = 0ULL; sim[p] = 0ULL; }

    // ---- pass 1: two halves, step-2 local scan ----
    #pragma unroll 1
    for (int half = 0; half < 2; half++) {
        // stage half: thread-chunk c, j_local = 4q+e
        #pragma unroll
        for (int k = 0; k < 16; k++) {
            int f = t + k * 256;
            int c = f >> 4, q = f & 15;
            float4 v = gu4[c * 32 + half * 16 + q];
            float* d = su + (4 * q) * SUP + c;
            d[0] = v.x; d[SUP] = v.y; d[2 * SUP] = v.z; d[3 * SUP] = v.w;
        }
        __syncthreads();
        #pragma unroll 2
        for (int q = 0; q < 32; q++) {
            float ua = su[(2 * q) * SUP + t];
            float ub = su[(2 * q + 1) * SUP + t];
            u64 u1 = pk(ua, ua), u2 = pk(ub, ub);
            #pragma unroll
            for (int p = 0; p < 8; p++) {
                u64 vre = fma2(w1re[p], u1, u2);
                u64 vim = mul2(w1im[p], u1);
                u64 nre = fma2(w2re[p], sre[p], fma2(nw2im[p], sim[p], vre));
                sim[p] = fma2(w2re[p], sim[p], fma2(w2im[p], sre[p], vim));
                sre[p] = nre;
            }
        }
        __syncthreads();
    }
    #pragma unroll
    for (int p = 0; p < 8; p++) {
        float r0, r1, i0, i1; upk(sre[p], r0, r1); upk(sim[p], i0, i1);
        sst[(2 * p) * SUP + t] = make_float2(r0, i0);
        sst[(2 * p + 1) * SUP + t] = make_float2(r1, i1);
    }
    __syncthreads();

    // ---- combine over 256 chunk states (16 n x 16 groups) ----
    int n = t & 15, g = t >> 4;
    float wtr = g_wTre[h * NN + n], wti = g_wTim[h * NN + n];
    {
        float Ir = 0.f, Ii = 0.f;
        for (int j = 0; j < 16; j++) {
            float2 loc = sst[n * SUP + g * 16 + j];
            float nr = fmaf(wtr, Ir, fmaf(-wti, Ii, loc.x));
            Ii = fmaf(wtr, Ii, fmaf(wti, Ir, loc.y));
            Ir = nr;
        }
        gs[g * 16 + n] = make_float2(Ir, Ii);
    }
    __syncthreads();
    if (t < 16) {
        float wr = g_wT16re[h * NN + t], wi = g_wT16im[h * NN + t];
        float Pr = 0.f, Pi = 0.f;
        for (int gg = 0; gg < 16; gg++) {
            float2 tmp = gs[gg * 16 + t];
            gs[gg * 16 + t] = make_float2(Pr, Pi);
            float nr = fmaf(wr, Pr, fmaf(-wi, Pi, tmp.x));
            Pi = fmaf(wr, Pi, fmaf(wi, Pr, tmp.y));
            Pr = nr;
        }
    }
    __syncthreads();
    {
        float2 I0 = gs[g * 16 + n];
        float Ir = I0.x, Ii = I0.y;
        for (int j = 0; j < 16; j++) {
            int c = g * 16 + j;
            float2 loc = sst[n * SUP + c];
            sst[n * SUP + c] = make_float2(Ir, Ii);
            float nr = fmaf(wtr, Ir, fmaf(-wti, Ii, loc.x));
            Ii = fmaf(wtr, Ii, fmaf(wti, Ir, loc.y));
            Ir = nr;
        }
    }
    __syncthreads();

    // ---- pass 2: step-1 rescan with incoming state, halves re-staged ----
    #pragma unroll
    for (int p = 0; p < 8; p++) {
        float2 a = sst[(2 * p) * SUP + t];
        float2 bq = sst[(2 * p + 1) * SUP + t];
        sre[p] = pk(a.x, bq.x);
        sim[p] = pk(a.y, bq.y);
    }
    // pass-2 constants: w1 (kept), nw1im, 2C' (neg im)
    u64 nw1im[8], cre2[8], ncim2[8];
    {
        const u64* pcr = reinterpret_cast<const u64*>(g_cre + h * NN);
        const u64* pci = reinterpret_cast<const u64*>(g_cim + h * NN);
        #pragma unroll
        for (int p = 0; p < 8; p++) {
            nw1im[p] = w1im[p] ^ NEGMASK;
            cre2[p] = pcr[p];
            ncim2[p] = pci[p] ^ NEGMASK;
        }
    }
    float dcoef = Dp[h];
    float gam = g_gamma[bh];
    float bet = g_beta[bh];
    float4* gz4 = reinterpret_cast<float4*>(g_z + (size_t)bh * LL);

    #pragma unroll 1
    for (int half = 0; half < 2; half++) {
        #pragma unroll
        for (int k = 0; k < 16; k++) {
            int f = t + k * 256;
            int c = f >> 4, q = f & 15;
            float4 v = gu4[c * 32 + half * 16 + q];
            float* d = su + (4 * q) * SUP + c;
            d[0] = v.x; d[SUP] = v.y; d[2 * SUP] = v.z; d[3 * SUP] = v.w;
        }
        __syncthreads();
        #pragma unroll 2
        for (int j = 0; j < 64; j++) {
            float uv = su[j * SUP + t];
            u64 u2 = pk(uv, uv);
            u64 accA = 0ULL, accB = 0ULL;
            #pragma unroll
            for (int p = 0; p < 8; p++) {
                u64 t0 = fma2(nw1im[p], sim[p], u2);
                u64 nre = fma2(w1re[p], sre[p], t0);
                sim[p] = fma2(w1re[p], sim[p], mul2(w1im[p], sre[p]));
                sre[p] = nre;
                accA = fma2(cre2[p], nre, accA);
                accB = fma2(ncim2[p], sim[p], accB);
            }
            u64 acc = add2(accA, accB);
            float alo, ahi; upk(acc, alo, ahi);
            float y = fmaf(dcoef, uv, alo + ahi);
            su[j * SUP + t] = fmaf(y, gam, bet);
        }
        __syncthreads();
        #pragma unroll
        for (int k = 0; k < 16; k++) {
            int f = t + k * 256;
            int c = f >> 4, q = f & 15;
            const float* s = su + (4 * q) * SUP + c;
            float4 o = make_float4(s[0], s[SUP], s[2 * SUP], s[3 * SUP]);
            gz4[c * 32 + half * 16 + q] = o;
        }
        __syncthreads();
    }
}

// ---------------- K4: out[b,l,h] = x[b,l,h] * gelu(z[b,h,l]) ----------------
__global__ __launch_bounds__(256) void k_epilogue(const float* __restrict__ x,
                                                  float* __restrict__ out)
{
    __shared__ float zt[64 * 65];
    int t = threadIdx.x;
    int b = blockIdx.x >> 9;
    int tile = blockIdx.x & 511;
    int l0 = tile * 64;

    #pragma unroll
    for (int i = t; i < 1024; i += 256) {
        int hh = i >> 4, q = i & 15;
        float4 v = *reinterpret_cast<const float4*>(
            g_z + ((size_t)b * HH + hh) * LL + l0 + 4 * q);
        float* d = zt + hh * 65 + 4 * q;
        d[0] = v.x; d[1] = v.y; d[2] = v.z; d[3] = v.w;
    }
    __syncthreads();

    #pragma unroll
    for (int i = t; i < 1024; i += 256) {
        int l = i >> 4, hq = i & 15;
        float z0 = zt[(4 * hq + 0) * 65 + l];
        float z1 = zt[(4 * hq + 1) * 65 + l];
        float z2 = zt[(4 * hq + 2) * 65 + l];
        float z3 = zt[(4 * hq + 3) * 65 + l];
        size_t base = ((size_t)b * LL + l0 + l) * HH + 4 * hq;
        float4 xv = *reinterpret_cast<const float4*>(x + base);
        float4 o;
        o.x = xv.x * gelu_f(z0);
        o.y = xv.y * gelu_f(z1);
        o.z = xv.z * gelu_f(z2);
        o.w = xv.w * gelu_f(z3);
        *reinterpret_cast<float4*>(out + base) = o;
    }
}

// ---------------- launch ----------------
extern "C" void kernel_launch(void* const* d_in, const int* in_sizes, int n_in,
                              void* d_out, int out_size)
{
    const float* x      = (const float*)d_in[0];
    const float* cp     = (const float*)d_in[1];
    const float* W0     = (const float*)d_in[2];
    const float* b0     = (const float*)d_in[3];
    const float* W1     = (const float*)d_in[4];
    const float* b1     = (const float*)d_in[5];
    const float* W2     = (const float*)d_in[6];
    const float* b2     = (const float*)d_in[7];
    const float* W_lin  = (const float*)d_in[8];
    const float* b_lin  = (const float*)d_in[9];
    const float* log_dt = (const float*)d_in[10];
    const float* A_re   = (const float*)d_in[11];
    const float* A_im   = (const float*)d_in[12];
    const float* C_re   = (const float*)d_in[13];
    const float* C_im   = (const float*)d_in[14];
    const float* Dv     = (const float*)d_in[15];
    const float* W_film = (const float*)d_in[16];
    const float* b_film = (const float*)d_in[17];
    float* out = (float*)d_out;

    const int smem_lin  = (256 * 65 + 64 * 64) * 4;
    const int smem_scan = (64 * SUP + 16 * SUP * 2 + 16 * 16 * 2) * 4;   // 100736 B
    cudaFuncSetAttribute(k_linear, cudaFuncAttributeMaxDynamicSharedMemorySize, smem_lin);
    cudaFuncSetAttribute(k_scan, cudaFuncAttributeMaxDynamicSharedMemorySize, smem_scan);

    k_setup_ssm<<<8, 128>>>(log_dt, A_re, A_im, C_re, C_im);
    k_setup_mlp<<<1, 256>>>(cp, W0, b0, W1, b1, W2, b2, W_film, b_film);
    k_linear<<<BB * (LL / 256), 256, smem_lin>>>(x, W_lin, b_lin);
    k_scan<<<BB * HH, 256, smem_scan>>>(Dv);
    k_epilogue<<<BB * (LL / 64), 256>>>(x, out);
}

// round 5
// speedup vs baseline: 1.4347x; 1.4347x over previous
#include <cuda_runtime.h>
#include <cstdint>
#include <cstddef>

#define BB 16
#define LL 32768
#define HH 64
#define NN 16
#define DMM 32

typedef unsigned long long u64;

// ---------------- scratch (device globals) ----------------
__device__ float g_u[(size_t)BB * HH * LL];   // gelu(x@W_lin) transposed to [B,H,L]
__device__ float g_z[(size_t)BB * HH * LL];   // FiLM-affine SSM output [B,H,L]
__device__ __align__(16) float g_w1re[HH * NN], g_w1im[HH * NN];
__device__ __align__(16) float g_w2re[HH * NN], g_w2im[HH * NN];
__device__ __align__(16) float g_cre[HH * NN], g_cim[HH * NN];     // 2*C'
__device__ float g_wTre[HH * NN], g_wTim[HH * NN];     // w^128
__device__ float g_wT16re[HH * NN], g_wT16im[HH * NN]; // w^2048
__device__ float g_gamma[BB * HH], g_beta[BB * HH];

// ---------------- f32x2 helpers ----------------
__device__ __forceinline__ u64 pk(float lo, float hi) {
    u64 r; asm("mov.b64 %0, {%1,%2};" : "=l"(r) : "f"(lo), "f"(hi)); return r;
}
__device__ __forceinline__ void upk(u64 a, float& lo, float& hi) {
    asm("mov.b64 {%0,%1}, %2;" : "=f"(lo), "=f"(hi) : "l"(a));
}
__device__ __forceinline__ u64 fma2(u64 a, u64 b, u64 c) {
    u64 d; asm("fma.rn.f32x2 %0, %1, %2, %3;" : "=l"(d) : "l"(a), "l"(b), "l"(c)); return d;
}
__device__ __forceinline__ u64 mul2(u64 a, u64 b) {
    u64 d; asm("mul.rn.f32x2 %0, %1, %2;" : "=l"(d) : "l"(a), "l"(b)); return d;
}
__device__ __forceinline__ u64 add2(u64 a, u64 b) {
    u64 d; asm("add.rn.f32x2 %0, %1, %2;" : "=l"(d) : "l"(a), "l"(b)); return d;
}
#define NEGMASK 0x8000000080000000ULL

// jax.nn.gelu (approximate=True)
__device__ __forceinline__ float gelu_f(float x) {
    float x3 = x * x * x;
    float z = 0.7978845608028654f * fmaf(0.044715f, x3, x);
    float az = fabsf(z);
    float e = __expf(2.0f * az);
    float t = 1.0f - __fdividef(2.0f, e + 1.0f);
    t = copysignf(t, z);
    return 0.5f * x * (1.0f + t);
}

// ---------------- K0: SSM constants ----------------
__global__ void k_setup_ssm(const float* __restrict__ log_dt,
                            const float* __restrict__ A_re, const float* __restrict__ A_im,
                            const float* __restrict__ C_re, const float* __restrict__ C_im)
{
    int i = blockIdx.x * blockDim.x + threadIdx.x;
    if (i >= HH * NN) return;
    int h = i / NN;
    float dt = expf(log_dt[h]);
    float ar = A_re[i], ai = A_im[i];
    double mre = (double)dt * (double)ar, mim = (double)dt * (double)ai;

    double e1 = exp(mre);
    float wre = (float)(e1 * cos(mim)), wim = (float)(e1 * sin(mim));
    g_w1re[i] = wre; g_w1im[i] = wim;
    double e2 = exp(2.0 * mre);
    g_w2re[i] = (float)(e2 * cos(2.0 * mim)); g_w2im[i] = (float)(e2 * sin(2.0 * mim));
    double eT = exp(128.0 * mre);
    g_wTre[i] = (float)(eT * cos(128.0 * mim)); g_wTim[i] = (float)(eT * sin(128.0 * mim));
    double eG = exp(2048.0 * mre);
    g_wT16re[i] = (float)(eG * cos(2048.0 * mim)); g_wT16im[i] = (float)(eG * sin(2048.0 * mim));

    // C' = C * (exp(dtA)-1)/A ; store 2*C'
    float inv = 1.0f / (ar * ar + ai * ai);
    float nre = wre - 1.0f, nim = wim;
    float qre = (nre * ar + nim * ai) * inv;
    float qim = (nim * ar - nre * ai) * inv;
    float cr = C_re[i], ci = C_im[i];
    g_cre[i] = 2.0f * (cr * qre - ci * qim);
    g_cim[i] = 2.0f * (cr * qim + ci * qre);
}

// ---------------- K1: conditioning MLP + FiLM ----------------
__global__ void k_setup_mlp(const float* __restrict__ cp,
                            const float* __restrict__ W0, const float* __restrict__ b0,
                            const float* __restrict__ W1, const float* __restrict__ b1,
                            const float* __restrict__ W2, const float* __restrict__ b2,
                            const float* __restrict__ W_film, const float* __restrict__ b_film)
{
    __shared__ float c0[BB * DMM];
    __shared__ float c1[BB * DMM];
    int t = threadIdx.x;

    for (int i = t; i < BB * DMM; i += blockDim.x) {
        int b = i / DMM, d = i % DMM;
        float v = fmaf(cp[b * 2 + 0], W0[d], fmaf(cp[b * 2 + 1], W0[DMM + d], b0[d]));
        c0[i] = gelu_f(v);
    }
    __syncthreads();
    for (int i = t; i < BB * DMM; i += blockDim.x) {
        int b = i / DMM, d = i % DMM;
        float v = b1[d];
        for (int k = 0; k < DMM; k++) v = fmaf(c0[b * DMM + k], W1[k * DMM + d], v);
        c1[i] = gelu_f(v);
    }
    __syncthreads();
    for (int i = t; i < BB * DMM; i += blockDim.x) {
        int b = i / DMM, d = i % DMM;
        float v = b2[d];
        for (int k = 0; k < DMM; k++) v = fmaf(c1[b * DMM + k], W2[k * DMM + d], v);
        c0[i] = gelu_f(v);
    }
    __syncthreads();
    for (int i = t; i < BB * 2 * HH; i += blockDim.x) {
        int b = i / (2 * HH), j = i % (2 * HH);
        float v = b_film[j];
        for (int k = 0; k < DMM; k++) v = fmaf(c0[b * DMM + k], W_film[k * 2 * HH + j], v);
        if (j < HH) g_gamma[b * HH + j] = v;
        else        g_beta[b * HH + j - HH] = v;
    }
}

// ---------------- K2: u = gelu(x @ W_lin + b_lin), write transposed [B,H,L] ----------------
__global__ __launch_bounds__(256) void k_linear(const float* __restrict__ x,
                                                const float* __restrict__ W,
                                                const float* __restrict__ bias)
{
    extern __shared__ float sm2[];
    float* xs = sm2;                 // [256][65]
    float* Ws = sm2 + 256 * 65;      // [64][64]
    int t = threadIdx.x;
    int b = blockIdx.x >> 7;
    int tile = blockIdx.x & 127;
    int l0 = tile * 256;
    const float* xg = x + ((size_t)b * LL + l0) * HH;

    for (int i = t; i < 64 * 64; i += 256) Ws[i] = W[i];
    for (int i = t; i < 256 * 64; i += 256) {
        int l = i >> 6, k = i & 63;
        xs[l * 65 + k] = xg[i];
    }
    __syncthreads();

    int li = t & 63;
    int hb = (t >> 6) * 16;
    u64 acc[4][8];
    #pragma unroll
    for (int p = 0; p < 8; p++) {
        u64 bp = *reinterpret_cast<const u64*>(bias + hb + 2 * p);
        acc[0][p] = bp; acc[1][p] = bp; acc[2][p] = bp; acc[3][p] = bp;
    }
    for (int k = 0; k < 64; k++) {
        float x0 = xs[li * 65 + k];
        float x1 = xs[(li + 64) * 65 + k];
        float x2v = xs[(li + 128) * 65 + k];
        float x3 = xs[(li + 192) * 65 + k];
        u64 xa = pk(x0, x0), xb = pk(x1, x1), xc = pk(x2v, x2v), xd = pk(x3, x3);
        const u64* wrow = reinterpret_cast<const u64*>(Ws + k * 64 + hb);
        #pragma unroll
        for (int p = 0; p < 8; p++) {
            u64 w2 = wrow[p];
            acc[0][p] = fma2(xa, w2, acc[0][p]);
            acc[1][p] = fma2(xb, w2, acc[1][p]);
            acc[2][p] = fma2(xc, w2, acc[2][p]);
            acc[3][p] = fma2(xd, w2, acc[3][p]);
        }
    }
    #pragma unroll
    for (int lg = 0; lg < 4; lg++) {
        int l = l0 + li + lg * 64;
        #pragma unroll
        for (int p = 0; p < 8; p++) {
            float v0, v1; upk(acc[lg][p], v0, v1);
            int h0 = hb + 2 * p;
            g_u[((size_t)b * HH + h0) * LL + l] = gelu_f(v0);
            g_u[((size_t)b * HH + h0 + 1) * LL + l] = gelu_f(v1);
        }
    }
}

// ---------------- K3: chunked parallel scan per (b,h), half-staged, 2 blocks/SM ----------------
// Thread t owns chunk l = t*128 + j, j = 0..127. SMEM holds 64 j-rows at a time:
// su[j_local*257 + t].  2 blocks/SM (101 KB smem, <=128 regs).
#define SUP 257
__global__ __launch_bounds__(256, 2) void k_scan(const float* __restrict__ Dp)
{
    extern __shared__ float sm[];
    float* su = sm;                                             // [64][257]
    float2* sst = reinterpret_cast<float2*>(sm + 64 * SUP);     // [16][257] float2
    float2* gs = reinterpret_cast<float2*>(sm + 64 * SUP + 16 * SUP * 2); // [16][16]
    int t = threadIdx.x;
    int bh = blockIdx.x;
    int h = bh & 63;

    const float4* gu4 = reinterpret_cast<const float4*>(g_u + (size_t)bh * LL);

    // pass-1 constants
    u64 w1re[8], w1im[8], w2re[8], w2im[8], nw2im[8];
    {
        const u64* p1r = reinterpret_cast<const u64*>(g_w1re + h * NN);
        const u64* p1i = reinterpret_cast<const u64*>(g_w1im + h * NN);
        const u64* p2r = reinterpret_cast<const u64*>(g_w2re + h * NN);
        const u64* p2i = reinterpret_cast<const u64*>(g_w2im + h * NN);
        #pragma unroll
        for (int p = 0; p < 8; p++) {
            w1re[p] = p1r[p]; w1im[p] = p1i[p];
            w2re[p] = p2r[p]; w2im[p] = p2i[p];
            nw2im[p] = p2i[p] ^ NEGMASK;
        }
    }

    u64 sre[8], sim[8];
    #pragma unroll
    for (int p = 0; p < 8; p++) { sre[p] = 0ULL; sim[p] = 0ULL; }

    // ---- pass 1: two halves, step-2 local scan ----
    #pragma unroll 1
    for (int half = 0; half < 2; half++) {
        // stage half: thread-chunk c, j_local = 4q+e
        #pragma unroll
        for (int k = 0; k < 16; k++) {
            int f = t + k * 256;
            int c = f >> 4, q = f & 15;
            float4 v = gu4[c * 32 + half * 16 + q];
            float* d = su + (4 * q) * SUP + c;
            d[0] = v.x; d[SUP] = v.y; d[2 * SUP] = v.z; d[3 * SUP] = v.w;
        }
        __syncthreads();
        #pragma unroll 2
        for (int q = 0; q < 32; q++) {
            float ua = su[(2 * q) * SUP + t];
            float ub = su[(2 * q + 1) * SUP + t];
            u64 u1 = pk(ua, ua), u2 = pk(ub, ub);
            #pragma unroll
            for (int p = 0; p < 8; p++) {
                u64 vre = fma2(w1re[p], u1, u2);
                u64 vim = mul2(w1im[p], u1);
                u64 nre = fma2(w2re[p], sre[p], fma2(nw2im[p], sim[p], vre));
                sim[p] = fma2(w2re[p], sim[p], fma2(w2im[p], sre[p], vim));
                sre[p] = nre;
            }
        }
        __syncthreads();
    }
    #pragma unroll
    for (int p = 0; p < 8; p++) {
        float r0, r1, i0, i1; upk(sre[p], r0, r1); upk(sim[p], i0, i1);
        sst[(2 * p) * SUP + t] = make_float2(r0, i0);
        sst[(2 * p + 1) * SUP + t] = make_float2(r1, i1);
    }
    __syncthreads();

    // ---- combine over 256 chunk states (16 n x 16 groups) ----
    int n = t & 15, g = t >> 4;
    float wtr = g_wTre[h * NN + n], wti = g_wTim[h * NN + n];
    {
        float Ir = 0.f, Ii = 0.f;
        for (int j = 0; j < 16; j++) {
            float2 loc = sst[n * SUP + g * 16 + j];
            float nr = fmaf(wtr, Ir, fmaf(-wti, Ii, loc.x));
            Ii = fmaf(wtr, Ii, fmaf(wti, Ir, loc.y));
            Ir = nr;
        }
        gs[g * 16 + n] = make_float2(Ir, Ii);
    }
    __syncthreads();
    if (t < 16) {
        float wr = g_wT16re[h * NN + t], wi = g_wT16im[h * NN + t];
        float Pr = 0.f, Pi = 0.f;
        for (int gg = 0; gg < 16; gg++) {
            float2 tmp = gs[gg * 16 + t];
            gs[gg * 16 + t] = make_float2(Pr, Pi);
            float nr = fmaf(wr, Pr, fmaf(-wi, Pi, tmp.x));
            Pi = fmaf(wr, Pi, fmaf(wi, Pr, tmp.y));
            Pr = nr;
        }
    }
    __syncthreads();
    {
        float2 I0 = gs[g * 16 + n];
        float Ir = I0.x, Ii = I0.y;
        for (int j = 0; j < 16; j++) {
            int c = g * 16 + j;
            float2 loc = sst[n * SUP + c];
            sst[n * SUP + c] = make_float2(Ir, Ii);
            float nr = fmaf(wtr, Ir, fmaf(-wti, Ii, loc.x));
            Ii = fmaf(wtr, Ii, fmaf(wti, Ir, loc.y));
            Ir = nr;
        }
    }
    __syncthreads();

    // ---- pass 2: step-1 rescan with incoming state, halves re-staged ----
    #pragma unroll
    for (int p = 0; p < 8; p++) {
        float2 a = sst[(2 * p) * SUP + t];
        float2 bq = sst[(2 * p + 1) * SUP + t];
        sre[p] = pk(a.x, bq.x);
        sim[p] = pk(a.y, bq.y);
    }
    // pass-2 constants: w1 (kept), nw1im, 2C' (neg im)
    u64 nw1im[8], cre2[8], ncim2[8];
    {
        const u64* pcr = reinterpret_cast<const u64*>(g_cre + h * NN);
        const u64* pci = reinterpret_cast<const u64*>(g_cim + h * NN);
        #pragma unroll
        for (int p = 0; p < 8; p++) {
            nw1im[p] = w1im[p] ^ NEGMASK;
            cre2[p] = pcr[p];
            ncim2[p] = pci[p] ^ NEGMASK;
        }
    }
    float dcoef = Dp[h];
    float gam = g_gamma[bh];
    float bet = g_beta[bh];
    float4* gz4 = reinterpret_cast<float4*>(g_z + (size_t)bh * LL);

    #pragma unroll 1
    for (int half = 0; half < 2; half++) {
        #pragma unroll
        for (int k = 0; k < 16; k++) {
            int f = t + k * 256;
            int c = f >> 4, q = f & 15;
            float4 v = gu4[c * 32 + half * 16 + q];
            float* d = su + (4 * q) * SUP + c;
            d[0] = v.x; d[SUP] = v.y; d[2 * SUP] = v.z; d[3 * SUP] = v.w;
        }
        __syncthreads();
        #pragma unroll 2
        for (int j = 0; j < 64; j++) {
            float uv = su[j * SUP + t];
            u64 u2 = pk(uv, uv);
            u64 accA = 0ULL, accB = 0ULL;
            #pragma unroll
            for (int p = 0; p < 8; p++) {
                u64 t0 = fma2(nw1im[p], sim[p], u2);
                u64 nre = fma2(w1re[p], sre[p], t0);
                sim[p] = fma2(w1re[p], sim[p], mul2(w1im[p], sre[p]));
                sre[p] = nre;
                accA = fma2(cre2[p], nre, accA);
                accB = fma2(ncim2[p], sim[p], accB);
            }
            u64 acc = add2(accA, accB);
            float alo, ahi; upk(acc, alo, ahi);
            float y = fmaf(dcoef, uv, alo + ahi);
            su[j * SUP + t] = fmaf(y, gam, bet);
        }
        __syncthreads();
        #pragma unroll
        for (int k = 0; k < 16; k++) {
            int f = t + k * 256;
            int c = f >> 4, q = f & 15;
            const float* s = su + (4 * q) * SUP + c;
            float4 o = make_float4(s[0], s[SUP], s[2 * SUP], s[3 * SUP]);
            gz4[c * 32 + half * 16 + q] = o;
        }
        __syncthreads();
    }
}

// ---------------- K4: out[b,l,h] = x[b,l,h] * gelu(z[b,h,l]) ----------------
__global__ __launch_bounds__(256) void k_epilogue(const float* __restrict__ x,
                                                  float* __restrict__ out)
{
    __shared__ float zt[64 * 65];
    int t = threadIdx.x;
    int b = blockIdx.x >> 9;
    int tile = blockIdx.x & 511;
    int l0 = tile * 64;

    #pragma unroll
    for (int i = t; i < 1024; i += 256) {
        int hh = i >> 4, q = i & 15;
        float4 v = *reinterpret_cast<const float4*>(
            g_z + ((size_t)b * HH + hh) * LL + l0 + 4 * q);
        float* d = zt + hh * 65 + 4 * q;
        d[0] = v.x; d[1] = v.y; d[2] = v.z; d[3] = v.w;
    }
    __syncthreads();

    #pragma unroll
    for (int i = t; i < 1024; i += 256) {
        int l = i >> 4, hq = i & 15;
        float z0 = zt[(4 * hq + 0) * 65 + l];
        float z1 = zt[(4 * hq + 1) * 65 + l];
        float z2 = zt[(4 * hq + 2) * 65 + l];
        float z3 = zt[(4 * hq + 3) * 65 + l];
        size_t base = ((size_t)b * LL + l0 + l) * HH + 4 * hq;
        float4 xv = *reinterpret_cast<const float4*>(x + base);
        float4 o;
        o.x = xv.x * gelu_f(z0);
        o.y = xv.y * gelu_f(z1);
        o.z = xv.z * gelu_f(z2);
        o.w = xv.w * gelu_f(z3);
        *reinterpret_cast<float4*>(out + base) = o;
    }
}

// ---------------- launch ----------------
extern "C" void kernel_launch(void* const* d_in, const int* in_sizes, int n_in,
                              void* d_out, int out_size)
{
    const float* x      = (const float*)d_in[0];
    const float* cp     = (const float*)d_in[1];
    const float* W0     = (const float*)d_in[2];
    const float* b0     = (const float*)d_in[3];
    const float* W1     = (const float*)d_in[4];
    const float* b1     = (const float*)d_in[5];
    const float* W2     = (const float*)d_in[6];
    const float* b2     = (const float*)d_in[7];
    const float* W_lin  = (const float*)d_in[8];
    const float* b_lin  = (const float*)d_in[9];
    const float* log_dt = (const float*)d_in[10];
    const float* A_re   = (const float*)d_in[11];
    const float* A_im   = (const float*)d_in[12];
    const float* C_re   = (const float*)d_in[13];
    const float* C_im   = (const float*)d_in[14];
    const float* Dv     = (const float*)d_in[15];
    const float* W_film = (const float*)d_in[16];
    const float* b_film = (const float*)d_in[17];
    float* out = (float*)d_out;

    const int smem_lin  = (256 * 65 + 64 * 64) * 4;
    const int smem_scan = (64 * SUP + 16 * SUP * 2 + 16 * 16 * 2) * 4;   // 100736 B
    cudaFuncSetAttribute(k_linear, cudaFuncAttributeMaxDynamicSharedMemorySize, smem_lin);
    cudaFuncSetAttribute(k_scan, cudaFuncAttributeMaxDynamicSharedMemorySize, smem_scan);

    k_setup_ssm<<<8, 128>>>(log_dt, A_re, A_im, C_re, C_im);
    k_setup_mlp<<<1, 256>>>(cp, W0, b0, W1, b1, W2, b2, W_film, b_film);
    k_linear<<<BB * (LL / 256), 256, smem_lin>>>(x, W_lin, b_lin);
    k_scan<<<BB * HH, 256, smem_scan>>>(Dv);
    k_epilogue<<<BB * (LL / 64), 256>>>(x, out);
}